// round 3
// baseline (speedup 1.0000x reference)
#include <cuda_runtime.h>
#include <cuda_fp16.h>
#include <stdint.h>

namespace {

constexpr int M  = 32;
constexpr int N  = 11008;
constexpr int K  = 4096;
constexpr int NT = 64;              // output channels per CTA
constexpr int KC = 128;             // K elements staged per iteration
constexpr int NITER = K / KC;       // 32
constexpr int WT_STRIDE = KC + 8;   // 136 halves = 272B rows (17x16B): conflict-free ldmatrix
constexpr int WT_HALVES = NT * WT_STRIDE;          // 8704
constexpr int XT_HALVES = M  * WT_STRIDE;          // 4352
constexpr int BUF_HALVES = WT_HALVES + XT_HALVES;  // 13056
constexpr int SMEM_BYTES = 2 * BUF_HALVES * 2;     // 52224

__device__ __forceinline__ void ldsm4(uint32_t r[4], uint32_t a) {
    asm volatile("ldmatrix.sync.aligned.m8n8.x4.shared.b16 {%0,%1,%2,%3}, [%4];"
                 : "=r"(r[0]), "=r"(r[1]), "=r"(r[2]), "=r"(r[3]) : "r"(a));
}

__device__ __forceinline__ void ldsm2(uint32_t r[2], uint32_t a) {
    asm volatile("ldmatrix.sync.aligned.m8n8.x2.shared.b16 {%0,%1}, [%2];"
                 : "=r"(r[0]), "=r"(r[1]) : "r"(a));
}

__device__ __forceinline__ void mma16816(float c[4], const uint32_t a[4], const uint32_t b[2]) {
    asm volatile(
        "mma.sync.aligned.m16n8k16.row.col.f32.f16.f16.f32 "
        "{%0,%1,%2,%3}, {%4,%5,%6,%7}, {%8,%9}, {%0,%1,%2,%3};"
        : "+f"(c[0]), "+f"(c[1]), "+f"(c[2]), "+f"(c[3])
        : "r"(a[0]), "r"(a[1]), "r"(a[2]), "r"(a[3]), "r"(b[0]), "r"(b[1]));
}

__device__ __forceinline__ uint32_t h2_u32(__half2 h) {
    return *reinterpret_cast<uint32_t*>(&h);
}

__device__ __forceinline__ uint32_t hsub2_u(uint32_t a, uint32_t b) {
    uint32_t d;
    asm("sub.f16x2 %0, %1, %2;" : "=r"(d) : "r"(a), "r"(b));
    return d;
}

// 16 packed int8 -> 16 fp16 exact (mode 2 path)
__device__ __forceinline__ void convert16(uint4 v, uint32_t h[8]) {
    const uint32_t BIAS = 0x64806480u;   // half2(1152, 1152)
    uint32_t w[4] = {v.x, v.y, v.z, v.w};
#pragma unroll
    for (int j = 0; j < 4; ++j) {
        uint32_t q = w[j] ^ 0x80808080u;
        h[2 * j]     = hsub2_u(__byte_perm(q, 0x64646464u, 0x4140), BIAS);
        h[2 * j + 1] = hsub2_u(__byte_perm(q, 0x64646464u, 0x4342), BIAS);
    }
}

__global__ void __launch_bounds__(256, 2)
qlinear_kernel(const float* __restrict__ x, const uint32_t* __restrict__ qw,
               const float* __restrict__ scales, const float* __restrict__ bias,
               float* __restrict__ out)
{
    extern __shared__ __half sm[];

    const int tid  = threadIdx.x;
    const int lane = tid & 31;
    const int warp = tid >> 5;
    const int wn   = warp & 3;   // n16 slot within CTA tile
    const int kg   = warp >> 2;  // k-group within staged chunk
    const int o0   = blockIdx.x * NT;

    // ---- uniform dtype probe on qweight: 0=int32, 1=float32, 2=packed int8 ----
    int mode;
    {
        uint32_t all_int = 1u, all_f = 1u;
#pragma unroll
        for (int i = 0; i < 8; ++i) {
            uint32_t w = __ldg(qw + i);
            all_int &= ((w + 128u) < 256u) ? 1u : 0u;
            uint32_t e = (w >> 23) & 0xFFu;
            all_f &= ((e >= 127u && e <= 134u) || w == 0u) ? 1u : 0u;
        }
        mode = all_int ? 0 : (all_f ? 1 : 2);
    }
    const uint8_t* qw8 = reinterpret_cast<const uint8_t*>(qw);

    uint4 wreg[8], xreg[4];

    auto ldg = [&](int it) {
        const int kc = it * KC;
        if (mode == 2) {
#pragma unroll
            for (int p = 0; p < 2; ++p) {
                int g = p * 256 + tid;            // 512 granules: 64 rows x 8x16B
                wreg[p] = *reinterpret_cast<const uint4*>(
                    qw8 + (size_t)(o0 + (g >> 3)) * K + kc + (g & 7) * 16);
            }
        } else {
#pragma unroll
            for (int p = 0; p < 8; ++p) {
                int g = p * 256 + tid;            // 2048 granules: 64 rows x 32x16B
                wreg[p] = *reinterpret_cast<const uint4*>(
                    qw + (size_t)(o0 + (g >> 5)) * K + kc + (g & 31) * 4);
            }
        }
#pragma unroll
        for (int p = 0; p < 4; ++p) {
            int g = p * 256 + tid;                // 1024 granules: 32 rows x 32x16B
            xreg[p] = *reinterpret_cast<const uint4*>(
                x + (size_t)(g >> 5) * K + kc + (g & 31) * 4);
        }
    };

    auto sts = [&](int b) {
        __half* wt = sm + b * BUF_HALVES;
        __half* xt = wt + WT_HALVES;
        if (mode == 2) {
#pragma unroll
            for (int p = 0; p < 2; ++p) {
                int g = p * 256 + tid;
                uint32_t h[8];
                convert16(wreg[p], h);
                uint4* dst = reinterpret_cast<uint4*>(
                    reinterpret_cast<uint8_t*>(wt) + (g >> 3) * (WT_STRIDE * 2) + (g & 7) * 32);
                dst[0] = make_uint4(h[0], h[1], h[2], h[3]);
                dst[1] = make_uint4(h[4], h[5], h[6], h[7]);
            }
        } else {
#pragma unroll
            for (int p = 0; p < 8; ++p) {
                int g = p * 256 + tid;
                float f0, f1, f2, f3;
                if (mode == 0) {
                    f0 = (float)(int)wreg[p].x; f1 = (float)(int)wreg[p].y;
                    f2 = (float)(int)wreg[p].z; f3 = (float)(int)wreg[p].w;
                } else {
                    f0 = __uint_as_float(wreg[p].x); f1 = __uint_as_float(wreg[p].y);
                    f2 = __uint_as_float(wreg[p].z); f3 = __uint_as_float(wreg[p].w);
                }
                uint32_t h01 = h2_u32(__floats2half2_rn(f0, f1));
                uint32_t h23 = h2_u32(__floats2half2_rn(f2, f3));
                *reinterpret_cast<uint2*>(
                    reinterpret_cast<uint8_t*>(wt) + (g >> 5) * (WT_STRIDE * 2) + (g & 31) * 8)
                    = make_uint2(h01, h23);
            }
        }
#pragma unroll
        for (int p = 0; p < 4; ++p) {
            int g = p * 256 + tid;
            float f0 = __uint_as_float(xreg[p].x), f1 = __uint_as_float(xreg[p].y);
            float f2 = __uint_as_float(xreg[p].z), f3 = __uint_as_float(xreg[p].w);
            uint32_t h01 = h2_u32(__floats2half2_rn(f0, f1));
            uint32_t h23 = h2_u32(__floats2half2_rn(f2, f3));
            *reinterpret_cast<uint2*>(
                reinterpret_cast<uint8_t*>(xt) + (g >> 5) * (WT_STRIDE * 2) + (g & 31) * 8)
                = make_uint2(h01, h23);
        }
    };

    // ldmatrix lane->address maps (byte offsets within tiles)
    const int rowA  = ((lane >> 3) & 1) * 8 + (lane & 7);
    const int colA  = (lane >> 4) * 8;
    const int laneB = lane & 15;
    const int rowB  = laneB & 7;
    const int colB  = (laneB >> 3) * 8;
    const uint32_t aoff0 = ((0 + rowA) * WT_STRIDE + colA) * 2;
    const uint32_t aoff1 = ((16 + rowA) * WT_STRIDE + colA) * 2;
    const uint32_t boff0 = ((wn * 16 + 0 + rowB) * WT_STRIDE + colB) * 2;
    const uint32_t boff1 = ((wn * 16 + 8 + rowB) * WT_STRIDE + colB) * 2;

    float acc[2][2][4];
#pragma unroll
    for (int i = 0; i < 2; ++i)
#pragma unroll
        for (int j = 0; j < 2; ++j)
#pragma unroll
            for (int e = 0; e < 4; ++e) acc[i][j][e] = 0.f;

    auto compute = [&](int b) {
        const __half* wt = sm + b * BUF_HALVES;
        const __half* xt = wt + WT_HALVES;
        const uint32_t wbase = (uint32_t)__cvta_generic_to_shared(wt);
        const uint32_t xbase = (uint32_t)__cvta_generic_to_shared(xt);
#pragma unroll
        for (int s = 0; s < 4; ++s) {
            const uint32_t koff = (uint32_t)(kg * 64 + s * 16) * 2;
            uint32_t a0[4], a1[4], bf0[2], bf1[2];
            ldsm4(a0, xbase + aoff0 + koff);
            ldsm4(a1, xbase + aoff1 + koff);
            ldsm2(bf0, wbase + boff0 + koff);
            ldsm2(bf1, wbase + boff1 + koff);
            mma16816(acc[0][0], a0, bf0);
            mma16816(acc[0][1], a0, bf1);
            mma16816(acc[1][0], a1, bf0);
            mma16816(acc[1][1], a1, bf1);
        }
    };

    // ---- pipeline ----
    ldg(0);
    sts(0);
    __syncthreads();

    for (int it = 0; it < NITER; ++it) {
        if (it + 1 < NITER) ldg(it + 1);
        compute(it & 1);
        if (it + 1 < NITER) sts((it + 1) & 1);
        __syncthreads();
    }

    // ---- split-K reduction across kg pairs ----
    float* red = reinterpret_cast<float*>(sm);   // 8 KB, buffers dead now
    if (kg == 1) {
#pragma unroll
        for (int i = 0; i < 2; ++i)
#pragma unroll
            for (int j = 0; j < 2; ++j)
#pragma unroll
                for (int e = 0; e < 4; ++e)
                    red[((wn * 32 + lane) * 16) + (i * 2 + j) * 4 + e] = acc[i][j][e];
    }
    __syncthreads();
    if (kg == 0) {
#pragma unroll
        for (int i = 0; i < 2; ++i)
#pragma unroll
            for (int j = 0; j < 2; ++j)
#pragma unroll
                for (int e = 0; e < 4; ++e)
                    acc[i][j][e] += red[((wn * 32 + lane) * 16) + (i * 2 + j) * 4 + e];

        // ---- epilogue: scale + bias in f32, round to fp16 values, store f32 ----
        const int gm = lane >> 2;
        const int gn = (lane & 3) * 2;
#pragma unroll
        for (int nt = 0; nt < 2; ++nt) {
            const int o = o0 + wn * 16 + nt * 8 + gn;
            const float s0 = scales[o];
            const float s1 = scales[o + 1];
            const float b0 = bias[o];
            const float b1 = bias[o + 1];
#pragma unroll
            for (int mt = 0; mt < 2; ++mt) {
                const float* c = acc[mt][nt];
                const int r0 = mt * 16 + gm;
                float2 v0, v1;
                v0.x = __half2float(__float2half_rn(c[0] * s0 + b0));
                v0.y = __half2float(__float2half_rn(c[1] * s1 + b1));
                v1.x = __half2float(__float2half_rn(c[2] * s0 + b0));
                v1.y = __half2float(__float2half_rn(c[3] * s1 + b1));
                *reinterpret_cast<float2*>(out + (size_t)r0 * N + o) = v0;
                *reinterpret_cast<float2*>(out + (size_t)(r0 + 8) * N + o) = v1;
            }
        }
    }
}

} // anonymous namespace

extern "C" void kernel_launch(void* const* d_in, const int* in_sizes, int n_in,
                              void* d_out, int out_size) {
    const float*    x  = reinterpret_cast<const float*>(d_in[0]);
    const uint32_t* qw = reinterpret_cast<const uint32_t*>(d_in[1]);
    const float*    sc = reinterpret_cast<const float*>(d_in[2]);
    const float*    bi = reinterpret_cast<const float*>(d_in[3]);
    float*          o  = reinterpret_cast<float*>(d_out);

    cudaFuncSetAttribute(qlinear_kernel,
                         cudaFuncAttributeMaxDynamicSharedMemorySize, SMEM_BYTES);
    qlinear_kernel<<<N / NT, 256, SMEM_BYTES>>>(x, qw, sc, bi, o);
}